// round 10
// baseline (speedup 1.0000x reference)
#include <cuda_runtime.h>

// Problem constants
#define B_   2
#define N_   65536
#define M_   16384
#define C1_  128
#define C2_  256
#define K1_  384     // C1 + C2
#define H_   256     // mlp[1]
#define O_   128     // mlp[2]
#define EPS_ 1e-5f

// ---------------- scratch (device globals; no runtime allocation) ----------------
__device__ float g_y1[(size_t)B_ * H_ * N_];   // raw layer-1 output (B,H,N)
__device__ int   g_idx[B_ * N_];               // 1-NN indices
__device__ float g_s1[H_], g_b1[H_];           // BN1 fused scale/bias
__device__ float g_s2[O_], g_b2[O_];           // BN2 fused scale/bias

// TF32 round-to-nearest-away (the cublas/cutlass operand rounding).
__device__ __forceinline__ float tf32r(float x) {
    float y;
    asm("cvt.rna.tf32.f32 %0, %1;" : "=f"(y) : "f"(x));
    return y;
}

// ============================================================================
// Kernel 1: 1-NN search — bitwise replica of the reference arithmetic.
//   u2 = rn(rn(rn(ux*ux)+rn(uy*uy))+rn(uz*uz))        (elementwise XLA)
//   k2 = same form on known coords
//   dot = fma chain ascending k, acc from 0            (cublas SIMT sgemm K=3)
//   d  = rn(rn(u2 - rn(2*dot)) + k2)                   (elementwise XLA)
//   argmin: strict-less scan, first (lowest) index wins ties — matches the
//   reference's chunked scan (per-chunk first-argmin + strict cross-chunk).
// ============================================================================
#define NN_T  128
#define NN_Q  2
#define NN_CH 2048

__global__ __launch_bounds__(NN_T)
void nn_kernel(const float* __restrict__ unknown, const float* __restrict__ known) {
    const int blocksPerB = N_ / (NN_T * NN_Q);          // 256
    const int b  = blockIdx.x / blocksPerB;
    const int j0 = (blockIdx.x % blocksPerB) * (NN_T * NN_Q);

    __shared__ float4 sk[NN_CH];

    const int tid = threadIdx.x;
    const int ja = j0 + tid;
    const int jb = j0 + tid + NN_T;

    const float* ua = unknown + ((size_t)b * N_ + ja) * 3;
    const float* ub = unknown + ((size_t)b * N_ + jb) * 3;
    const float ux0 = ua[0], uy0 = ua[1], uz0 = ua[2];
    const float ux1 = ub[0], uy1 = ub[1], uz1 = ub[2];

    const float u20 = __fadd_rn(__fadd_rn(__fmul_rn(ux0, ux0), __fmul_rn(uy0, uy0)),
                                __fmul_rn(uz0, uz0));
    const float u21 = __fadd_rn(__fadd_rn(__fmul_rn(ux1, ux1), __fmul_rn(uy1, uy1)),
                                __fmul_rn(uz1, uz1));

    float best0 = INFINITY, best1 = INFINITY;
    int   bi0 = 0, bi1 = 0;

    for (int cb = 0; cb < M_; cb += NN_CH) {
        __syncthreads();
        for (int i = tid; i < NN_CH; i += NN_T) {
            const float* kp = known + ((size_t)b * M_ + cb + i) * 3;
            const float x = kp[0], y = kp[1], z = kp[2];
            const float k2 = __fadd_rn(__fadd_rn(__fmul_rn(x, x), __fmul_rn(y, y)),
                                       __fmul_rn(z, z));
            sk[i] = make_float4(x, y, z, k2);
        }
        __syncthreads();

#pragma unroll 8
        for (int s = 0; s < NN_CH; s++) {
            const float4 k = sk[s];
            // dot: ascending-k fma chain (acc starts at 0 -> first step = rounded mul)
            float t0 = __fmul_rn(ux0, k.x);
            t0 = __fmaf_rn(uy0, k.y, t0);
            t0 = __fmaf_rn(uz0, k.z, t0);
            float t1 = __fmul_rn(ux1, k.x);
            t1 = __fmaf_rn(uy1, k.y, t1);
            t1 = __fmaf_rn(uz1, k.z, t1);
            const float d0 = __fadd_rn(__fsub_rn(u20, __fadd_rn(t0, t0)), k.w);
            const float d1 = __fadd_rn(__fsub_rn(u21, __fadd_rn(t1, t1)), k.w);
            if (d0 < best0) { best0 = d0; bi0 = cb + s; }
            if (d1 < best1) { best1 = d1; bi1 = cb + s; }
        }
    }
    g_idx[(size_t)b * N_ + ja] = bi0;
    g_idx[(size_t)b * N_ + jb] = bi1;
}

// ============================================================================
// Kernel 2: GEMM1 (TF32-emulated) with fused gather+concat.
// y1(b, 0:256, j) = w1[:, 0:256] @ known_feats[b,:,idx[j]]
//                 + w1[:, 256:384] @ unknow_feats[b,:,j]
// Operands rounded to TF32 (rna) when staged to smem; fp32 fma accumulate.
// CTA tile: 256 x 128, K=384, BK=16; 512 threads, 8x8 microtile.
// ============================================================================
#define G1_BK 16

__global__ __launch_bounds__(512)
void gemm1_kernel(const float* __restrict__ kf, const float* __restrict__ uf,
                  const float* __restrict__ w1) {
    const int b  = blockIdx.y;
    const int j0 = blockIdx.x * 128;

    __shared__ float Ws[G1_BK][260];   // [k][c], padded row to break bank conflicts
    __shared__ float Xs[G1_BK][132];   // [k][j]
    __shared__ int   sidx[128];

    const int tid = threadIdx.x;
    if (tid < 128) sidx[tid] = g_idx[(size_t)b * N_ + j0 + tid];
    __syncthreads();

    const float* kfb = kf + (size_t)b * C2_ * M_;
    const float* ufb = uf + (size_t)b * C1_ * N_;

    float acc[8][8];
#pragma unroll
    for (int i = 0; i < 8; i++)
#pragma unroll
        for (int j = 0; j < 8; j++) acc[i][j] = 0.f;

    const int ty = tid >> 4;    // 0..31 -> rows ty*8
    const int tx = tid & 15;    // 0..15 -> cols tx*8
    const int jj    = tid & 127;
    const int kbase = tid >> 7; // 0..3

    for (int kk = 0; kk < K1_; kk += G1_BK) {
        // W tile: Ws[k][c] = tf32(w1[c*384 + kk + k])
#pragma unroll
        for (int r = 0; r < 2; r++) {
            const int L  = tid + r * 512;
            const int c  = L >> 2;
            const int k4 = (L & 3) * 4;
            const float4 v = *(const float4*)(w1 + (size_t)c * K1_ + kk + k4);
            Ws[k4 + 0][c] = tf32r(v.x); Ws[k4 + 1][c] = tf32r(v.y);
            Ws[k4 + 2][c] = tf32r(v.z); Ws[k4 + 3][c] = tf32r(v.w);
        }
        // X tile: gathered known_feats for kg<256, streamed unknow_feats after
#pragma unroll
        for (int r = 0; r < 4; r++) {
            const int k  = kbase + r * 4;
            const int kg = kk + k;
            float v;
            if (kg < C2_) v = __ldg(kfb + (size_t)kg * M_ + sidx[jj]);
            else          v = ufb[(size_t)(kg - C2_) * N_ + j0 + jj];
            Xs[k][jj] = tf32r(v);
        }
        __syncthreads();

#pragma unroll
        for (int k = 0; k < G1_BK; k++) {
            float a[8], x[8];
            *(float4*)&a[0] = *(const float4*)&Ws[k][ty * 8];
            *(float4*)&a[4] = *(const float4*)&Ws[k][ty * 8 + 4];
            *(float4*)&x[0] = *(const float4*)&Xs[k][tx * 8];
            *(float4*)&x[4] = *(const float4*)&Xs[k][tx * 8 + 4];
#pragma unroll
            for (int i = 0; i < 8; i++)
#pragma unroll
                for (int j = 0; j < 8; j++)
                    acc[i][j] = fmaf(a[i], x[j], acc[i][j]);
        }
        __syncthreads();
    }

    float* yb = g_y1 + (size_t)b * H_ * N_;
#pragma unroll
    for (int i = 0; i < 8; i++) {
        const int c = ty * 8 + i;
        float* p = yb + (size_t)c * N_ + j0 + tx * 8;
        *(float4*)p       = make_float4(acc[i][0], acc[i][1], acc[i][2], acc[i][3]);
        *(float4*)(p + 4) = make_float4(acc[i][4], acc[i][5], acc[i][6], acc[i][7]);
    }
}

// ============================================================================
// Kernel 3: per-channel BN stats -> fused scale/bias.
// One block per channel; reduces B*N values. which==1 -> (g_y1, g_s1/g_b1),
// which==2 -> (extdata(=d_out), g_s2/g_b2).
// ============================================================================
__global__ __launch_bounds__(256)
void stats_kernel(const float* __restrict__ extdata,
                  const float* __restrict__ gamma, const float* __restrict__ beta,
                  int C, int which) {
    const float* src = (which == 1) ? g_y1 : extdata;
    const int c   = blockIdx.x;
    const int tid = threadIdx.x;

    float sum = 0.f, sq = 0.f;
    for (int b = 0; b < B_; b++) {
        const float4* p = (const float4*)(src + ((size_t)b * C + c) * N_);
#pragma unroll 4
        for (int i = tid; i < N_ / 4; i += 256) {
            const float4 v = p[i];
            sum += v.x + v.y + v.z + v.w;
            sq = fmaf(v.x, v.x, sq); sq = fmaf(v.y, v.y, sq);
            sq = fmaf(v.z, v.z, sq); sq = fmaf(v.w, v.w, sq);
        }
    }
    __shared__ float ssum[256], ssq[256];
    ssum[tid] = sum; ssq[tid] = sq;
    __syncthreads();
    for (int st = 128; st > 0; st >>= 1) {
        if (tid < st) { ssum[tid] += ssum[tid + st]; ssq[tid] += ssq[tid + st]; }
        __syncthreads();
    }
    if (tid == 0) {
        const float inv  = 1.f / (float)(B_ * N_);
        const float mean = ssum[0] * inv;
        const float var  = ssq[0] * inv - mean * mean;
        const float s    = gamma[c] * rsqrtf(var + EPS_);
        if (which == 1) { g_s1[c] = s; g_b1[c] = beta[c] - mean * s; }
        else            { g_s2[c] = s; g_b2[c] = beta[c] - mean * s; }
    }
}

// ============================================================================
// Kernel 4: GEMM2 (TF32-emulated) with BN1+ReLU fused into the operand load.
// y2(b, 0:128, j) = w2 @ tf32(relu(s1*y1 + b1)).  Raw y2 written into d_out.
// CTA tile 128x128, K=256, BK=16; 256 threads, 8x8 microtile.
// ============================================================================
__global__ __launch_bounds__(256)
void gemm2_kernel(const float* __restrict__ w2, float* __restrict__ dout) {
    const int b  = blockIdx.y;
    const int j0 = blockIdx.x * 128;

    __shared__ float Ws[16][132];
    __shared__ float Xs[16][132];
    __shared__ float ss[H_], sb[H_];

    const int tid = threadIdx.x;
    ss[tid] = g_s1[tid];
    sb[tid] = g_b1[tid];
    __syncthreads();

    const float* y1b = g_y1 + (size_t)b * H_ * N_;

    float acc[8][8];
#pragma unroll
    for (int i = 0; i < 8; i++)
#pragma unroll
        for (int j = 0; j < 8; j++) acc[i][j] = 0.f;

    const int ty = tid >> 4;   // 0..15
    const int tx = tid & 15;   // 0..15

    for (int kk = 0; kk < H_; kk += 16) {
#pragma unroll
        for (int r = 0; r < 2; r++) {
            const int L  = tid + r * 256;       // 0..511
            const int c  = L >> 2;              // 0..127
            const int k4 = (L & 3) * 4;
            const float4 v = *(const float4*)(w2 + (size_t)c * H_ + kk + k4);
            Ws[k4 + 0][c] = tf32r(v.x); Ws[k4 + 1][c] = tf32r(v.y);
            Ws[k4 + 2][c] = tf32r(v.z); Ws[k4 + 3][c] = tf32r(v.w);
        }
#pragma unroll
        for (int r = 0; r < 2; r++) {
            const int L  = tid + r * 256;       // 0..511
            const int k  = L >> 5;              // 0..15
            const int j4 = (L & 31) * 4;
            const int kg = kk + k;
            float4 v = *(const float4*)(y1b + (size_t)kg * N_ + j0 + j4);
            const float s = ss[kg], bb = sb[kg];
            v.x = tf32r(fmaxf(fmaf(s, v.x, bb), 0.f));
            v.y = tf32r(fmaxf(fmaf(s, v.y, bb), 0.f));
            v.z = tf32r(fmaxf(fmaf(s, v.z, bb), 0.f));
            v.w = tf32r(fmaxf(fmaf(s, v.w, bb), 0.f));
            *(float4*)&Xs[k][j4] = v;
        }
        __syncthreads();

#pragma unroll
        for (int k = 0; k < 16; k++) {
            float a[8], x[8];
            *(float4*)&a[0] = *(const float4*)&Ws[k][ty * 8];
            *(float4*)&a[4] = *(const float4*)&Ws[k][ty * 8 + 4];
            *(float4*)&x[0] = *(const float4*)&Xs[k][tx * 8];
            *(float4*)&x[4] = *(const float4*)&Xs[k][tx * 8 + 4];
#pragma unroll
            for (int i = 0; i < 8; i++)
#pragma unroll
                for (int j = 0; j < 8; j++)
                    acc[i][j] = fmaf(a[i], x[j], acc[i][j]);
        }
        __syncthreads();
    }

    float* ob = dout + (size_t)b * O_ * N_;
#pragma unroll
    for (int i = 0; i < 8; i++) {
        const int c = ty * 8 + i;
        float* p = ob + (size_t)c * N_ + j0 + tx * 8;
        *(float4*)p       = make_float4(acc[i][0], acc[i][1], acc[i][2], acc[i][3]);
        *(float4*)(p + 4) = make_float4(acc[i][4], acc[i][5], acc[i][6], acc[i][7]);
    }
}

// ============================================================================
// Kernel 5: in-place BN2 + ReLU on d_out.
// ============================================================================
__global__ __launch_bounds__(256)
void apply2_kernel(float* __restrict__ dout) {
    const size_t total4 = (size_t)B_ * O_ * N_ / 4;
    for (size_t i = (size_t)blockIdx.x * blockDim.x + threadIdx.x; i < total4;
         i += (size_t)gridDim.x * blockDim.x) {
        float4 v = ((float4*)dout)[i];
        const int c = (int)((i * 4) >> 16) & (O_ - 1);   // N_ = 2^16
        const float s = g_s2[c], bb = g_b2[c];
        v.x = fmaxf(fmaf(s, v.x, bb), 0.f);
        v.y = fmaxf(fmaf(s, v.y, bb), 0.f);
        v.z = fmaxf(fmaf(s, v.z, bb), 0.f);
        v.w = fmaxf(fmaf(s, v.w, bb), 0.f);
        ((float4*)dout)[i] = v;
    }
}

// ============================================================================
extern "C" void kernel_launch(void* const* d_in, const int* in_sizes, int n_in,
                              void* d_out, int out_size) {
    (void)in_sizes; (void)n_in; (void)out_size;
    const float* unknown = (const float*)d_in[0];
    const float* known   = (const float*)d_in[1];
    const float* uf      = (const float*)d_in[2];
    const float* kf      = (const float*)d_in[3];
    const float* w1      = (const float*)d_in[4];
    const float* gamma1  = (const float*)d_in[5];
    const float* beta1   = (const float*)d_in[6];
    const float* w2      = (const float*)d_in[7];
    const float* gamma2  = (const float*)d_in[8];
    const float* beta2   = (const float*)d_in[9];
    float* out = (float*)d_out;

    nn_kernel<<<(B_ * N_) / (NN_T * NN_Q), NN_T>>>(unknown, known);
    gemm1_kernel<<<dim3(N_ / 128, B_), 512>>>(kf, uf, w1);
    stats_kernel<<<H_, 256>>>(nullptr, gamma1, beta1, H_, 1);
    gemm2_kernel<<<dim3(N_ / 128, B_), 256>>>(w2, out);
    stats_kernel<<<O_, 256>>>(out, gamma2, beta2, O_, 2);
    apply2_kernel<<<2048, 256>>>(out);
}

// round 12
// speedup vs baseline: 1.0010x; 1.0010x over previous
#include <cuda_runtime.h>

// Problem constants
#define B_   2
#define N_   65536
#define M_   16384
#define C1_  128
#define C2_  256
#define K1_  384     // C1 + C2
#define H_   256     // mlp[1]
#define O_   128     // mlp[2]
#define EPS_ 1e-5f

// ---------------- scratch (device globals; no runtime allocation) ----------------
__device__ float g_y1[(size_t)B_ * H_ * N_];   // raw layer-1 output (B,H,N)
__device__ int   g_idx[B_ * N_];               // 1-NN indices
__device__ float g_s1[H_], g_b1[H_];           // BN1 fused scale/bias
__device__ float g_s2[O_], g_b2[O_];           // BN2 fused scale/bias

// TF32 round-to-nearest-away (the cublas/cutlass operand rounding).
__device__ __forceinline__ float tf32r(float x) {
    float y;
    asm("cvt.rna.tf32.f32 %0, %1;" : "=f"(y) : "f"(x));
    return y;
}

// ============================================================================
// Kernel 1: 1-NN search — bitwise replica of the reference arithmetic.
//   u2 = rn(rn(rn(ux*ux)+rn(uy*uy))+rn(uz*uz))        (elementwise XLA)
//   k2 = same form on known coords
//   dot = fma chain ascending k, acc from 0            (cublas SIMT sgemm K=3)
//   d  = rn(rn(u2 - rn(2*dot)) + k2)                   (elementwise XLA)
//   argmin: strict-less scan, first (lowest) index wins ties — matches the
//   reference's chunked scan (per-chunk first-argmin + strict cross-chunk).
// ============================================================================
#define NN_T  128
#define NN_Q  2
#define NN_CH 2048

__global__ __launch_bounds__(NN_T)
void nn_kernel(const float* __restrict__ unknown, const float* __restrict__ known) {
    const int blocksPerB = N_ / (NN_T * NN_Q);          // 256
    const int b  = blockIdx.x / blocksPerB;
    const int j0 = (blockIdx.x % blocksPerB) * (NN_T * NN_Q);

    __shared__ float4 sk[NN_CH];

    const int tid = threadIdx.x;
    const int ja = j0 + tid;
    const int jb = j0 + tid + NN_T;

    const float* ua = unknown + ((size_t)b * N_ + ja) * 3;
    const float* ub = unknown + ((size_t)b * N_ + jb) * 3;
    const float ux0 = ua[0], uy0 = ua[1], uz0 = ua[2];
    const float ux1 = ub[0], uy1 = ub[1], uz1 = ub[2];

    const float u20 = __fadd_rn(__fadd_rn(__fmul_rn(ux0, ux0), __fmul_rn(uy0, uy0)),
                                __fmul_rn(uz0, uz0));
    const float u21 = __fadd_rn(__fadd_rn(__fmul_rn(ux1, ux1), __fmul_rn(uy1, uy1)),
                                __fmul_rn(uz1, uz1));

    float best0 = INFINITY, best1 = INFINITY;
    int   bi0 = 0, bi1 = 0;

    for (int cb = 0; cb < M_; cb += NN_CH) {
        __syncthreads();
        for (int i = tid; i < NN_CH; i += NN_T) {
            const float* kp = known + ((size_t)b * M_ + cb + i) * 3;
            const float x = kp[0], y = kp[1], z = kp[2];
            const float k2 = __fadd_rn(__fadd_rn(__fmul_rn(x, x), __fmul_rn(y, y)),
                                       __fmul_rn(z, z));
            sk[i] = make_float4(x, y, z, k2);
        }
        __syncthreads();

#pragma unroll 8
        for (int s = 0; s < NN_CH; s++) {
            const float4 k = sk[s];
            // dot: ascending-k fma chain (acc starts at 0 -> first step = rounded mul)
            float t0 = __fmul_rn(ux0, k.x);
            t0 = __fmaf_rn(uy0, k.y, t0);
            t0 = __fmaf_rn(uz0, k.z, t0);
            float t1 = __fmul_rn(ux1, k.x);
            t1 = __fmaf_rn(uy1, k.y, t1);
            t1 = __fmaf_rn(uz1, k.z, t1);
            const float d0 = __fadd_rn(__fsub_rn(u20, __fadd_rn(t0, t0)), k.w);
            const float d1 = __fadd_rn(__fsub_rn(u21, __fadd_rn(t1, t1)), k.w);
            if (d0 < best0) { best0 = d0; bi0 = cb + s; }
            if (d1 < best1) { best1 = d1; bi1 = cb + s; }
        }
    }
    g_idx[(size_t)b * N_ + ja] = bi0;
    g_idx[(size_t)b * N_ + jb] = bi1;
}

// ============================================================================
// Kernel 2: GEMM1 (TF32-emulated) with fused gather+concat.
// y1(b, 0:256, j) = w1[:, 0:256] @ known_feats[b,:,idx[j]]
//                 + w1[:, 256:384] @ unknow_feats[b,:,j]
// Operands rounded to TF32 (rna) when staged to smem; fp32 fma accumulate.
// CTA tile: 256 x 128, K=384, BK=16; 512 threads, 8x8 microtile.
// ============================================================================
#define G1_BK 16

__global__ __launch_bounds__(512)
void gemm1_kernel(const float* __restrict__ kf, const float* __restrict__ uf,
                  const float* __restrict__ w1) {
    const int b  = blockIdx.y;
    const int j0 = blockIdx.x * 128;

    __shared__ float Ws[G1_BK][260];   // [k][c], padded row to break bank conflicts
    __shared__ float Xs[G1_BK][132];   // [k][j]
    __shared__ int   sidx[128];

    const int tid = threadIdx.x;
    if (tid < 128) sidx[tid] = g_idx[(size_t)b * N_ + j0 + tid];
    __syncthreads();

    const float* kfb = kf + (size_t)b * C2_ * M_;
    const float* ufb = uf + (size_t)b * C1_ * N_;

    float acc[8][8];
#pragma unroll
    for (int i = 0; i < 8; i++)
#pragma unroll
        for (int j = 0; j < 8; j++) acc[i][j] = 0.f;

    const int ty = tid >> 4;    // 0..31 -> rows ty*8
    const int tx = tid & 15;    // 0..15 -> cols tx*8
    const int jj    = tid & 127;
    const int kbase = tid >> 7; // 0..3

    for (int kk = 0; kk < K1_; kk += G1_BK) {
        // W tile: Ws[k][c] = tf32(w1[c*384 + kk + k])
#pragma unroll
        for (int r = 0; r < 2; r++) {
            const int L  = tid + r * 512;
            const int c  = L >> 2;
            const int k4 = (L & 3) * 4;
            const float4 v = *(const float4*)(w1 + (size_t)c * K1_ + kk + k4);
            Ws[k4 + 0][c] = tf32r(v.x); Ws[k4 + 1][c] = tf32r(v.y);
            Ws[k4 + 2][c] = tf32r(v.z); Ws[k4 + 3][c] = tf32r(v.w);
        }
        // X tile: gathered known_feats for kg<256, streamed unknow_feats after
#pragma unroll
        for (int r = 0; r < 4; r++) {
            const int k  = kbase + r * 4;
            const int kg = kk + k;
            float v;
            if (kg < C2_) v = __ldg(kfb + (size_t)kg * M_ + sidx[jj]);
            else          v = ufb[(size_t)(kg - C2_) * N_ + j0 + jj];
            Xs[k][jj] = tf32r(v);
        }
        __syncthreads();

#pragma unroll
        for (int k = 0; k < G1_BK; k++) {
            float a[8], x[8];
            *(float4*)&a[0] = *(const float4*)&Ws[k][ty * 8];
            *(float4*)&a[4] = *(const float4*)&Ws[k][ty * 8 + 4];
            *(float4*)&x[0] = *(const float4*)&Xs[k][tx * 8];
            *(float4*)&x[4] = *(const float4*)&Xs[k][tx * 8 + 4];
#pragma unroll
            for (int i = 0; i < 8; i++)
#pragma unroll
                for (int j = 0; j < 8; j++)
                    acc[i][j] = fmaf(a[i], x[j], acc[i][j]);
        }
        __syncthreads();
    }

    float* yb = g_y1 + (size_t)b * H_ * N_;
#pragma unroll
    for (int i = 0; i < 8; i++) {
        const int c = ty * 8 + i;
        float* p = yb + (size_t)c * N_ + j0 + tx * 8;
        *(float4*)p       = make_float4(acc[i][0], acc[i][1], acc[i][2], acc[i][3]);
        *(float4*)(p + 4) = make_float4(acc[i][4], acc[i][5], acc[i][6], acc[i][7]);
    }
}

// ============================================================================
// Kernel 3: per-channel BN stats -> fused scale/bias.
// One block per channel; reduces B*N values. which==1 -> (g_y1, g_s1/g_b1),
// which==2 -> (extdata(=d_out), g_s2/g_b2).
// ============================================================================
__global__ __launch_bounds__(256)
void stats_kernel(const float* __restrict__ extdata,
                  const float* __restrict__ gamma, const float* __restrict__ beta,
                  int C, int which) {
    const float* src = (which == 1) ? g_y1 : extdata;
    const int c   = blockIdx.x;
    const int tid = threadIdx.x;

    float sum = 0.f, sq = 0.f;
    for (int b = 0; b < B_; b++) {
        const float4* p = (const float4*)(src + ((size_t)b * C + c) * N_);
#pragma unroll 4
        for (int i = tid; i < N_ / 4; i += 256) {
            const float4 v = p[i];
            sum += v.x + v.y + v.z + v.w;
            sq = fmaf(v.x, v.x, sq); sq = fmaf(v.y, v.y, sq);
            sq = fmaf(v.z, v.z, sq); sq = fmaf(v.w, v.w, sq);
        }
    }
    __shared__ float ssum[256], ssq[256];
    ssum[tid] = sum; ssq[tid] = sq;
    __syncthreads();
    for (int st = 128; st > 0; st >>= 1) {
        if (tid < st) { ssum[tid] += ssum[tid + st]; ssq[tid] += ssq[tid + st]; }
        __syncthreads();
    }
    if (tid == 0) {
        const float inv  = 1.f / (float)(B_ * N_);
        const float mean = ssum[0] * inv;
        const float var  = ssq[0] * inv - mean * mean;
        const float s    = gamma[c] * rsqrtf(var + EPS_);
        if (which == 1) { g_s1[c] = s; g_b1[c] = beta[c] - mean * s; }
        else            { g_s2[c] = s; g_b2[c] = beta[c] - mean * s; }
    }
}

// ============================================================================
// Kernel 4: GEMM2 (TF32-emulated) with BN1+ReLU fused into the operand load.
// y2(b, 0:128, j) = w2 @ tf32(relu(s1*y1 + b1)).  Raw y2 written into d_out.
// CTA tile 128x128, K=256, BK=16; 256 threads, 8x8 microtile.
// ============================================================================
__global__ __launch_bounds__(256)
void gemm2_kernel(const float* __restrict__ w2, float* __restrict__ dout) {
    const int b  = blockIdx.y;
    const int j0 = blockIdx.x * 128;

    __shared__ float Ws[16][132];
    __shared__ float Xs[16][132];
    __shared__ float ss[H_], sb[H_];

    const int tid = threadIdx.x;
    ss[tid] = g_s1[tid];
    sb[tid] = g_b1[tid];
    __syncthreads();

    const float* y1b = g_y1 + (size_t)b * H_ * N_;

    float acc[8][8];
#pragma unroll
    for (int i = 0; i < 8; i++)
#pragma unroll
        for (int j = 0; j < 8; j++) acc[i][j] = 0.f;

    const int ty = tid >> 4;   // 0..15
    const int tx = tid & 15;   // 0..15

    for (int kk = 0; kk < H_; kk += 16) {
#pragma unroll
        for (int r = 0; r < 2; r++) {
            const int L  = tid + r * 256;       // 0..511
            const int c  = L >> 2;              // 0..127
            const int k4 = (L & 3) * 4;
            const float4 v = *(const float4*)(w2 + (size_t)c * H_ + kk + k4);
            Ws[k4 + 0][c] = tf32r(v.x); Ws[k4 + 1][c] = tf32r(v.y);
            Ws[k4 + 2][c] = tf32r(v.z); Ws[k4 + 3][c] = tf32r(v.w);
        }
#pragma unroll
        for (int r = 0; r < 2; r++) {
            const int L  = tid + r * 256;       // 0..511
            const int k  = L >> 5;              // 0..15
            const int j4 = (L & 31) * 4;
            const int kg = kk + k;
            float4 v = *(const float4*)(y1b + (size_t)kg * N_ + j0 + j4);
            const float s = ss[kg], bb = sb[kg];
            v.x = tf32r(fmaxf(fmaf(s, v.x, bb), 0.f));
            v.y = tf32r(fmaxf(fmaf(s, v.y, bb), 0.f));
            v.z = tf32r(fmaxf(fmaf(s, v.z, bb), 0.f));
            v.w = tf32r(fmaxf(fmaf(s, v.w, bb), 0.f));
            *(float4*)&Xs[k][j4] = v;
        }
        __syncthreads();

#pragma unroll
        for (int k = 0; k < 16; k++) {
            float a[8], x[8];
            *(float4*)&a[0] = *(const float4*)&Ws[k][ty * 8];
            *(float4*)&a[4] = *(const float4*)&Ws[k][ty * 8 + 4];
            *(float4*)&x[0] = *(const float4*)&Xs[k][tx * 8];
            *(float4*)&x[4] = *(const float4*)&Xs[k][tx * 8 + 4];
#pragma unroll
            for (int i = 0; i < 8; i++)
#pragma unroll
                for (int j = 0; j < 8; j++)
                    acc[i][j] = fmaf(a[i], x[j], acc[i][j]);
        }
        __syncthreads();
    }

    float* ob = dout + (size_t)b * O_ * N_;
#pragma unroll
    for (int i = 0; i < 8; i++) {
        const int c = ty * 8 + i;
        float* p = ob + (size_t)c * N_ + j0 + tx * 8;
        *(float4*)p       = make_float4(acc[i][0], acc[i][1], acc[i][2], acc[i][3]);
        *(float4*)(p + 4) = make_float4(acc[i][4], acc[i][5], acc[i][6], acc[i][7]);
    }
}

// ============================================================================
// Kernel 5: in-place BN2 + ReLU on d_out.
// ============================================================================
__global__ __launch_bounds__(256)
void apply2_kernel(float* __restrict__ dout) {
    const size_t total4 = (size_t)B_ * O_ * N_ / 4;
    for (size_t i = (size_t)blockIdx.x * blockDim.x + threadIdx.x; i < total4;
         i += (size_t)gridDim.x * blockDim.x) {
        float4 v = ((float4*)dout)[i];
        const int c = (int)((i * 4) >> 16) & (O_ - 1);   // N_ = 2^16
        const float s = g_s2[c], bb = g_b2[c];
        v.x = fmaxf(fmaf(s, v.x, bb), 0.f);
        v.y = fmaxf(fmaf(s, v.y, bb), 0.f);
        v.z = fmaxf(fmaf(s, v.z, bb), 0.f);
        v.w = fmaxf(fmaf(s, v.w, bb), 0.f);
        ((float4*)dout)[i] = v;
    }
}

// ============================================================================
extern "C" void kernel_launch(void* const* d_in, const int* in_sizes, int n_in,
                              void* d_out, int out_size) {
    (void)in_sizes; (void)n_in; (void)out_size;
    const float* unknown = (const float*)d_in[0];
    const float* known   = (const float*)d_in[1];
    const float* uf      = (const float*)d_in[2];
    const float* kf      = (const float*)d_in[3];
    const float* w1      = (const float*)d_in[4];
    const float* gamma1  = (const float*)d_in[5];
    const float* beta1   = (const float*)d_in[6];
    const float* w2      = (const float*)d_in[7];
    const float* gamma2  = (const float*)d_in[8];
    const float* beta2   = (const float*)d_in[9];
    float* out = (float*)d_out;

    nn_kernel<<<(B_ * N_) / (NN_T * NN_Q), NN_T>>>(unknown, known);
    gemm1_kernel<<<dim3(N_ / 128, B_), 512>>>(kf, uf, w1);
    stats_kernel<<<H_, 256>>>(nullptr, gamma1, beta1, H_, 1);
    gemm2_kernel<<<dim3(N_ / 128, B_), 256>>>(w2, out);
    stats_kernel<<<O_, 256>>>(out, gamma2, beta2, O_, 2);
    apply2_kernel<<<2048, 256>>>(out);
}

// round 14
// speedup vs baseline: 1.5313x; 1.5297x over previous
#include <cuda_runtime.h>
#include <cstdint>

// Problem constants
#define B_   2
#define N_   65536
#define M_   16384
#define C1_  128
#define C2_  256
#define K1_  384     // C1 + C2
#define H_   256     // mlp[1]
#define O_   128     // mlp[2]
#define EPS_ 1e-5f

// ---------------- scratch (device globals; no runtime allocation) ----------------
__device__ float g_y1t[(size_t)B_ * N_ * H_];  // layer-1 raw output, j-major: [b][n][256]
__device__ int   g_idx[B_ * N_];               // 1-NN indices
__device__ float g_s1[H_], g_b1[H_];           // BN1 fused scale/bias
__device__ float g_s2[O_], g_b2[O_];           // BN2 fused scale/bias
__device__ float g_p1s[256 * H_];              // stats1 partial sums [block][chan]
__device__ float g_p1q[256 * H_];              // stats1 partial sumsq

// TF32 round-to-nearest-away (operand rounding used by cublas; sm_80+ baseline)
__device__ __forceinline__ float tf32r(float x) {
    float y;
    asm("cvt.rna.tf32.f32 %0, %1;" : "=f"(y) : "f"(x));
    return y;
}

// mma.sync m16n8k8 TF32 (baseline PTX, not 'a'-gated). D += A*B, fp32 accum.
__device__ __forceinline__ void mma_tf32(float* d, const uint32_t* a, const uint32_t* b) {
    asm volatile(
        "mma.sync.aligned.m16n8k8.row.col.f32.tf32.tf32.f32 "
        "{%0,%1,%2,%3}, {%4,%5,%6,%7}, {%8,%9}, {%0,%1,%2,%3};"
        : "+f"(d[0]), "+f"(d[1]), "+f"(d[2]), "+f"(d[3])
        : "r"(a[0]), "r"(a[1]), "r"(a[2]), "r"(a[3]), "r"(b[0]), "r"(b[1]));
}

// ============================================================================
// Kernel 1: 1-NN search — bitwise replica of the reference arithmetic.
//   d = rn(rn(u2 - rn(2*t)) + k2); the inner pair is fused as fma(-2, t, u2),
//   bitwise identical because 2*t is exact in fp32.
// ============================================================================
#define NN_T  128
#define NN_Q  2
#define NN_CH 2048

__global__ __launch_bounds__(NN_T)
void nn_kernel(const float* __restrict__ unknown, const float* __restrict__ known) {
    const int blocksPerB = N_ / (NN_T * NN_Q);          // 256
    const int b  = blockIdx.x / blocksPerB;
    const int j0 = (blockIdx.x % blocksPerB) * (NN_T * NN_Q);

    __shared__ float4 sk[NN_CH];

    const int tid = threadIdx.x;
    const int ja = j0 + tid;
    const int jb = j0 + tid + NN_T;

    const float* ua = unknown + ((size_t)b * N_ + ja) * 3;
    const float* ub = unknown + ((size_t)b * N_ + jb) * 3;
    const float ux0 = ua[0], uy0 = ua[1], uz0 = ua[2];
    const float ux1 = ub[0], uy1 = ub[1], uz1 = ub[2];

    const float u20 = __fadd_rn(__fadd_rn(__fmul_rn(ux0, ux0), __fmul_rn(uy0, uy0)),
                                __fmul_rn(uz0, uz0));
    const float u21 = __fadd_rn(__fadd_rn(__fmul_rn(ux1, ux1), __fmul_rn(uy1, uy1)),
                                __fmul_rn(uz1, uz1));

    float best0 = INFINITY, best1 = INFINITY;
    int   bi0 = 0, bi1 = 0;

    for (int cb = 0; cb < M_; cb += NN_CH) {
        __syncthreads();
        for (int i = tid; i < NN_CH; i += NN_T) {
            const float* kp = known + ((size_t)b * M_ + cb + i) * 3;
            const float x = kp[0], y = kp[1], z = kp[2];
            const float k2 = __fadd_rn(__fadd_rn(__fmul_rn(x, x), __fmul_rn(y, y)),
                                       __fmul_rn(z, z));
            sk[i] = make_float4(x, y, z, k2);
        }
        __syncthreads();

#pragma unroll 8
        for (int s = 0; s < NN_CH; s++) {
            const float4 k = sk[s];
            float t0 = __fmul_rn(ux0, k.x);
            t0 = __fmaf_rn(uy0, k.y, t0);
            t0 = __fmaf_rn(uz0, k.z, t0);
            float t1 = __fmul_rn(ux1, k.x);
            t1 = __fmaf_rn(uy1, k.y, t1);
            t1 = __fmaf_rn(uz1, k.z, t1);
            const float d0 = __fadd_rn(__fmaf_rn(-2.0f, t0, u20), k.w);
            const float d1 = __fadd_rn(__fmaf_rn(-2.0f, t1, u21), k.w);
            if (d0 < best0) { best0 = d0; bi0 = cb + s; }
            if (d1 < best1) { best1 = d1; bi1 = cb + s; }
        }
    }
    g_idx[(size_t)b * N_ + ja] = bi0;
    g_idx[(size_t)b * N_ + jb] = bi1;
}

// ============================================================================
// Kernel 2: GEMM1 on mma.sync TF32, fused gather+concat.
//   y1t[b][j][c] = sum_k w1[c][k] * X[k][j],  X = concat(gathered kf, uf).
//   CTA: 512 thr (16 warps), tile M(c)=256 x N(j)=128, BK=32 (12 chunks).
//   Warp tile m64 x n32 (warps: wm=wid&3, wn=wid>>2).
//   smem stride 36 -> fragment LDS addresses hit banks (4g+t): conflict-free.
// ============================================================================
#define G1_SMEM ((256 * 36 + 128 * 36 + 128) * 4)   // sA + sB + sidx = 55808 B

__global__ __launch_bounds__(512, 1)
void gemm1_mma(const float* __restrict__ kf, const float* __restrict__ uf,
               const float* __restrict__ w1) {
    extern __shared__ float sm[];
    float* sA   = sm;                       // [256][36]
    float* sB   = sm + 256 * 36;            // [128][36]
    int*   sidx = (int*)(sm + 256 * 36 + 128 * 36);

    const int tid = threadIdx.x;
    const int j0  = blockIdx.x * 128;
    const int bb  = blockIdx.y;
    if (tid < 128) sidx[tid] = g_idx[(size_t)bb * N_ + j0 + tid];

    const float* kfb = kf + (size_t)bb * C2_ * M_;
    const float* ufb = uf + (size_t)bb * C1_ * N_;

    const int lane = tid & 31, wid = tid >> 5;
    const int wm = wid & 3, wn = wid >> 2;
    const int g = lane >> 2, t = lane & 3;

    float acc[4][4][4];
#pragma unroll
    for (int i = 0; i < 4; i++)
#pragma unroll
        for (int n = 0; n < 4; n++)
#pragma unroll
            for (int r = 0; r < 4; r++) acc[i][n][r] = 0.f;

    for (int kc = 0; kc < 12; kc++) {
        const int kk = kc * 32;
        __syncthreads();
        // ---- A staging: 256c x 32k, tf32-rounded ----
        {
            const int c = tid >> 1, half = tid & 1;
            const float* src = w1 + (size_t)c * K1_ + kk + half * 16;
            float* dst = sA + c * 36 + half * 16;
#pragma unroll
            for (int i = 0; i < 4; i++) {
                float4 v = *(const float4*)(src + i * 4);
                v.x = tf32r(v.x); v.y = tf32r(v.y); v.z = tf32r(v.z); v.w = tf32r(v.w);
                *(float4*)(dst + i * 4) = v;
            }
        }
        // ---- B staging: 128j x 32k (gather for k<256, stream for k>=256) ----
        {
            const int j = tid & 127, kq = tid >> 7;
            if (kk < C2_) {
                const int col = sidx[j];
#pragma unroll
                for (int i = 0; i < 8; i++)
                    sB[j * 36 + kq * 8 + i] =
                        tf32r(__ldg(kfb + (size_t)(kk + kq * 8 + i) * M_ + col));
            } else {
#pragma unroll
                for (int i = 0; i < 8; i++) {
                    const int kg = kk + kq * 8 + i - C2_;
                    sB[j * 36 + kq * 8 + i] = tf32r(ufb[(size_t)kg * N_ + j0 + j]);
                }
            }
        }
        __syncthreads();
        // ---- 4 k8 MMA steps ----
#pragma unroll
        for (int ks = 0; ks < 4; ks++) {
            const int k = ks * 8;
            uint32_t af[4][4], bf[4][2];
#pragma unroll
            for (int i = 0; i < 4; i++) {
                const float* pa = sA + (wm * 64 + i * 16 + g) * 36 + k + t;
                af[i][0] = __float_as_uint(pa[0]);
                af[i][1] = __float_as_uint(pa[8 * 36]);
                af[i][2] = __float_as_uint(pa[4]);
                af[i][3] = __float_as_uint(pa[8 * 36 + 4]);
            }
#pragma unroll
            for (int nt = 0; nt < 4; nt++) {
                const float* pb = sB + (wn * 32 + nt * 8 + g) * 36 + k + t;
                bf[nt][0] = __float_as_uint(pb[0]);
                bf[nt][1] = __float_as_uint(pb[4]);
            }
#pragma unroll
            for (int i = 0; i < 4; i++)
#pragma unroll
                for (int nt = 0; nt < 4; nt++)
                    mma_tf32(acc[i][nt], af[i], bf[nt]);
        }
    }

    // ---- Epilogue: transpose through smem (reuse sA), coalesced y1t writes ----
    float* E = sA;                      // [32][260]
    const int r  = tid >> 4;            // 0..31
    const int fq = tid & 15;
    for (int p = 0; p < 4; p++) {
        __syncthreads();
        if (wn == p) {
#pragma unroll
            for (int i = 0; i < 4; i++)
#pragma unroll
                for (int nt = 0; nt < 4; nt++) {
                    const int jl = nt * 8 + 2 * t;
                    const int c  = wm * 64 + i * 16 + g;
                    E[jl * 260 + c]           = acc[i][nt][0];
                    E[(jl + 1) * 260 + c]     = acc[i][nt][1];
                    E[jl * 260 + c + 8]       = acc[i][nt][2];
                    E[(jl + 1) * 260 + c + 8] = acc[i][nt][3];
                }
        }
        __syncthreads();
        float* yb = g_y1t + ((size_t)bb * N_ + j0 + p * 32) * H_;
#pragma unroll
        for (int i = 0; i < 4; i++) {
            const int c = (fq + i * 16) * 4;
            *(float4*)(yb + (size_t)r * H_ + c) = *(const float4*)(E + r * 260 + c);
        }
    }
}

// ============================================================================
// Kernel 3a/3b: BN1 stats on j-major y1t, deterministic two-stage partials.
// ============================================================================
__global__ __launch_bounds__(256)
void stats1a_kernel() {
    const int blk = blockIdx.x;                 // 256 blocks x 512 rows
    const int tid = threadIdx.x;
    const float* base = g_y1t + (size_t)blk * 512 * H_;

    float s[4] = {0, 0, 0, 0}, q[4] = {0, 0, 0, 0};
#pragma unroll 4
    for (int it = 0; it < 128; it++) {
        const float4 v = *(const float4*)(base + ((size_t)it * 256 + tid) * 4);
        s[0] += v.x; s[1] += v.y; s[2] += v.z; s[3] += v.w;
        q[0] = fmaf(v.x, v.x, q[0]); q[1] = fmaf(v.y, v.y, q[1]);
        q[2] = fmaf(v.z, v.z, q[2]); q[3] = fmaf(v.w, v.w, q[3]);
    }
    __shared__ float sh[256][8];
#pragma unroll
    for (int i = 0; i < 4; i++) { sh[tid][i] = s[i]; sh[tid][4 + i] = q[i]; }
    __syncthreads();
    if (tid < 64) {
#pragma unroll
        for (int i = 0; i < 4; i++) {
            float ss = sh[tid][i] + sh[tid + 64][i] + sh[tid + 128][i] + sh[tid + 192][i];
            float qq = sh[tid][4 + i] + sh[tid + 64][4 + i] + sh[tid + 128][4 + i] + sh[tid + 192][4 + i];
            g_p1s[blk * H_ + tid * 4 + i] = ss;
            g_p1q[blk * H_ + tid * 4 + i] = qq;
        }
    }
}

__global__ __launch_bounds__(256)
void stats1b_kernel(const float* __restrict__ gamma, const float* __restrict__ beta) {
    const int c = threadIdx.x;
    float s = 0.f, q = 0.f;
    for (int b = 0; b < 256; b++) { s += g_p1s[b * H_ + c]; q += g_p1q[b * H_ + c]; }
    const float inv  = 1.f / (float)(B_ * N_);
    const float mean = s * inv;
    const float var  = q * inv - mean * mean;
    const float sc   = gamma[c] * rsqrtf(var + EPS_);
    g_s1[c] = sc;
    g_b1[c] = beta[c] - mean * sc;
}

// ============================================================================
// Kernel 4: GEMM2 on mma.sync TF32 with BN1+ReLU fused into B staging.
//   out_raw[b][c][j] = w2 @ relu(bn1(y1t)).  CTA: 512 thr, tile 128c x 128j,
//   K=256 in 8 chunks of 32. Warp tile m64 x n16 (wm=wid&1, wn=wid>>1).
//   Epilogue: direct STG.64 (acc j-pairs are contiguous in d_out rows).
// ============================================================================
__global__ __launch_bounds__(512, 1)
void gemm2_mma(const float* __restrict__ w2, float* __restrict__ out) {
    __shared__ float sA[128 * 36];
    __shared__ float sB[128 * 36];
    __shared__ float ss[H_], sbv[H_];

    const int tid = threadIdx.x;
    const int j0  = blockIdx.x * 128;
    const int bb  = blockIdx.y;
    if (tid < 256) { ss[tid] = g_s1[tid]; sbv[tid] = g_b1[tid]; }

    const float* yb = g_y1t + ((size_t)bb * N_ + j0) * H_;

    const int lane = tid & 31, wid = tid >> 5;
    const int wm = wid & 1, wn = wid >> 1;
    const int g = lane >> 2, t = lane & 3;

    float acc[4][2][4];
#pragma unroll
    for (int i = 0; i < 4; i++)
#pragma unroll
        for (int n = 0; n < 2; n++)
#pragma unroll
            for (int r = 0; r < 4; r++) acc[i][n][r] = 0.f;

    for (int kc = 0; kc < 8; kc++) {
        const int kk = kc * 32;
        __syncthreads();
        // ---- A staging: 128c x 32k ----
        {
            const int c = tid >> 2, part = tid & 3;
            const float* src = w2 + (size_t)c * H_ + kk + part * 8;
            float* dst = sA + c * 36 + part * 8;
#pragma unroll
            for (int i = 0; i < 2; i++) {
                float4 v = *(const float4*)(src + i * 4);
                v.x = tf32r(v.x); v.y = tf32r(v.y); v.z = tf32r(v.z); v.w = tf32r(v.w);
                *(float4*)(dst + i * 4) = v;
            }
        }
        // ---- B staging: 128j x 32k, bn1+relu fused (coalesced float4) ----
        {
            const int j = tid >> 2, part = tid & 3;
            const float* src = yb + (size_t)j * H_ + kk + part * 8;
            float* dst = sB + j * 36 + part * 8;
#pragma unroll
            for (int i = 0; i < 2; i++) {
                const int k = kk + part * 8 + i * 4;
                float4 v = *(const float4*)(src + i * 4);
                v.x = tf32r(fmaxf(fmaf(ss[k],     v.x, sbv[k]),     0.f));
                v.y = tf32r(fmaxf(fmaf(ss[k + 1], v.y, sbv[k + 1]), 0.f));
                v.z = tf32r(fmaxf(fmaf(ss[k + 2], v.z, sbv[k + 2]), 0.f));
                v.w = tf32r(fmaxf(fmaf(ss[k + 3], v.w, sbv[k + 3]), 0.f));
                *(float4*)(dst + i * 4) = v;
            }
        }
        __syncthreads();
#pragma unroll
        for (int ks = 0; ks < 4; ks++) {
            const int k = ks * 8;
            uint32_t af[4][4], bf[2][2];
#pragma unroll
            for (int i = 0; i < 4; i++) {
                const float* pa = sA + (wm * 64 + i * 16 + g) * 36 + k + t;
                af[i][0] = __float_as_uint(pa[0]);
                af[i][1] = __float_as_uint(pa[8 * 36]);
                af[i][2] = __float_as_uint(pa[4]);
                af[i][3] = __float_as_uint(pa[8 * 36 + 4]);
            }
#pragma unroll
            for (int nt = 0; nt < 2; nt++) {
                const float* pb = sB + (wn * 16 + nt * 8 + g) * 36 + k + t;
                bf[nt][0] = __float_as_uint(pb[0]);
                bf[nt][1] = __float_as_uint(pb[4]);
            }
#pragma unroll
            for (int i = 0; i < 4; i++)
#pragma unroll
                for (int nt = 0; nt < 2; nt++)
                    mma_tf32(acc[i][nt], af[i], bf[nt]);
        }
    }

    // ---- Epilogue: direct stores (c-major out rows, j-pairs contiguous) ----
    float* ob = out + (size_t)bb * O_ * N_ + j0;
#pragma unroll
    for (int i = 0; i < 4; i++)
#pragma unroll
        for (int nt = 0; nt < 2; nt++) {
            const int c = wm * 64 + i * 16 + g;
            const int j = wn * 16 + nt * 8 + 2 * t;
            *(float2*)(ob + (size_t)c * N_ + j)       = make_float2(acc[i][nt][0], acc[i][nt][1]);
            *(float2*)(ob + (size_t)(c + 8) * N_ + j) = make_float2(acc[i][nt][2], acc[i][nt][3]);
        }
}

// ============================================================================
// Kernel 5: BN2 stats on d_out (c-major rows, coalesced).
// ============================================================================
__global__ __launch_bounds__(256)
void stats2_kernel(const float* __restrict__ src,
                   const float* __restrict__ gamma, const float* __restrict__ beta) {
    const int c   = blockIdx.x;
    const int tid = threadIdx.x;

    float sum = 0.f, sq = 0.f;
    for (int b = 0; b < B_; b++) {
        const float4* p = (const float4*)(src + ((size_t)b * O_ + c) * N_);
#pragma unroll 4
        for (int i = tid; i < N_ / 4; i += 256) {
            const float4 v = p[i];
            sum += v.x + v.y + v.z + v.w;
            sq = fmaf(v.x, v.x, sq); sq = fmaf(v.y, v.y, sq);
            sq = fmaf(v.z, v.z, sq); sq = fmaf(v.w, v.w, sq);
        }
    }
    __shared__ float ssum[256], ssq[256];
    ssum[tid] = sum; ssq[tid] = sq;
    __syncthreads();
    for (int st = 128; st > 0; st >>= 1) {
        if (tid < st) { ssum[tid] += ssum[tid + st]; ssq[tid] += ssq[tid + st]; }
        __syncthreads();
    }
    if (tid == 0) {
        const float inv  = 1.f / (float)(B_ * N_);
        const float mean = ssum[0] * inv;
        const float var  = ssq[0] * inv - mean * mean;
        const float s    = gamma[c] * rsqrtf(var + EPS_);
        g_s2[c] = s; g_b2[c] = beta[c] - mean * s;
    }
}

// ============================================================================
// Kernel 6: in-place BN2 + ReLU on d_out.
// ============================================================================
__global__ __launch_bounds__(256)
void apply2_kernel(float* __restrict__ dout) {
    const size_t total4 = (size_t)B_ * O_ * N_ / 4;
    for (size_t i = (size_t)blockIdx.x * blockDim.x + threadIdx.x; i < total4;
         i += (size_t)gridDim.x * blockDim.x) {
        float4 v = ((float4*)dout)[i];
        const int c = (int)((i * 4) >> 16) & (O_ - 1);   // N_ = 2^16
        const float s = g_s2[c], bb = g_b2[c];
        v.x = fmaxf(fmaf(s, v.x, bb), 0.f);
        v.y = fmaxf(fmaf(s, v.y, bb), 0.f);
        v.z = fmaxf(fmaf(s, v.z, bb), 0.f);
        v.w = fmaxf(fmaf(s, v.w, bb), 0.f);
        ((float4*)dout)[i] = v;
    }
}

// ============================================================================
extern "C" void kernel_launch(void* const* d_in, const int* in_sizes, int n_in,
                              void* d_out, int out_size) {
    (void)in_sizes; (void)n_in; (void)out_size;
    const float* unknown = (const float*)d_in[0];
    const float* known   = (const float*)d_in[1];
    const float* uf      = (const float*)d_in[2];
    const float* kf      = (const float*)d_in[3];
    const float* w1      = (const float*)d_in[4];
    const float* gamma1  = (const float*)d_in[5];
    const float* beta1   = (const float*)d_in[6];
    const float* w2      = (const float*)d_in[7];
    const float* gamma2  = (const float*)d_in[8];
    const float* beta2   = (const float*)d_in[9];
    float* out = (float*)d_out;

    static int s_init = 0;
    if (!s_init) {
        cudaFuncSetAttribute(gemm1_mma, cudaFuncAttributeMaxDynamicSharedMemorySize, G1_SMEM);
        s_init = 1;
    }

    nn_kernel<<<(B_ * N_) / (NN_T * NN_Q), NN_T>>>(unknown, known);
    gemm1_mma<<<dim3(N_ / 128, B_), 512, G1_SMEM>>>(kf, uf, w1);
    stats1a_kernel<<<256, 256>>>();
    stats1b_kernel<<<1, 256>>>(gamma1, beta1);
    gemm2_mma<<<dim3(N_ / 128, B_), 512>>>(w2, out);
    stats2_kernel<<<O_, 256>>>(out, gamma2, beta2);
    apply2_kernel<<<2048, 256>>>(out);
}

// round 15
// speedup vs baseline: 1.6803x; 1.0973x over previous
#include <cuda_runtime.h>
#include <cstdint>

// Problem constants
#define B_   2
#define N_   65536
#define M_   16384
#define C1_  128
#define C2_  256
#define K1_  384     // C1 + C2
#define H_   256     // mlp[1]
#define O_   128     // mlp[2]
#define EPS_ 1e-5f

// ---------------- scratch (device globals; no runtime allocation) ----------------
__device__ float g_y1t[(size_t)B_ * N_ * H_];  // layer-1 raw output, j-major: [b][n][256]
__device__ int   g_idx[B_ * N_];               // 1-NN indices
__device__ float g_s1[H_], g_b1[H_];           // BN1 fused scale/bias
__device__ float g_s2[O_], g_b2[O_];           // BN2 fused scale/bias
__device__ float g_p1s[H_ * 1024];             // stats1 partials [chan][block]
__device__ float g_p1q[H_ * 1024];
__device__ float g_p2s[O_ * 1024];             // stats2 partials [chan][block]
__device__ float g_p2q[O_ * 1024];

// TF32 round-to-nearest-away (operand rounding used by cublas; sm_80+ baseline)
__device__ __forceinline__ float tf32r(float x) {
    float y;
    asm("cvt.rna.tf32.f32 %0, %1;" : "=f"(y) : "f"(x));
    return y;
}

// mma.sync m16n8k8 TF32 (baseline PTX, not 'a'-gated). D += A*B, fp32 accum.
__device__ __forceinline__ void mma_tf32(float* d, const uint32_t* a, const uint32_t* b) {
    asm volatile(
        "mma.sync.aligned.m16n8k8.row.col.f32.tf32.tf32.f32 "
        "{%0,%1,%2,%3}, {%4,%5,%6,%7}, {%8,%9}, {%0,%1,%2,%3};"
        : "+f"(d[0]), "+f"(d[1]), "+f"(d[2]), "+f"(d[3])
        : "r"(a[0]), "r"(a[1]), "r"(a[2]), "r"(a[3]), "r"(b[0]), "r"(b[1]));
}

// ---------------- packed f32x2 helpers (PTX: requires sm_100+, family-portable) ----
typedef unsigned long long u64_t;
__device__ __forceinline__ u64_t pk2(float lo, float hi) {
    u64_t r; asm("mov.b64 %0, {%1, %2};" : "=l"(r) : "f"(lo), "f"(hi)); return r;
}
__device__ __forceinline__ u64_t mul2(u64_t a, u64_t b) {
    u64_t d; asm("mul.rn.f32x2 %0, %1, %2;" : "=l"(d) : "l"(a), "l"(b)); return d;
}
__device__ __forceinline__ u64_t fma2(u64_t a, u64_t b, u64_t c) {
    u64_t d; asm("fma.rn.f32x2 %0, %1, %2, %3;" : "=l"(d) : "l"(a), "l"(b), "l"(c)); return d;
}
__device__ __forceinline__ u64_t add2(u64_t a, u64_t b) {
    u64_t d; asm("add.rn.f32x2 %0, %1, %2;" : "=l"(d) : "l"(a), "l"(b)); return d;
}
__device__ __forceinline__ void upk2(u64_t v, float& lo, float& hi) {
    asm("mov.b64 {%0, %1}, %2;" : "=f"(lo), "=f"(hi) : "l"(v));
}

// ============================================================================
// Kernel 1: 1-NN search — bitwise replica of the reference arithmetic, two
// candidates per packed f32x2 lane-pair.  Per lane:
//   d = rn(rn(u2 - rn(2*t)) + k2), inner pair fused as fma(-2, t, u2)
//   (bitwise identical: 2*t is exact).  Lo-then-hi strict-less scan keeps
//   reference first-index tie-breaking.
// ============================================================================
#define NN_T  128
#define NN_Q  2
#define NN_CH 2048

__global__ __launch_bounds__(NN_T)
void nn_kernel(const float* __restrict__ unknown, const float* __restrict__ known) {
    const int blocksPerB = N_ / (NN_T * NN_Q);          // 256
    const int b  = blockIdx.x / blocksPerB;
    const int j0 = (blockIdx.x % blocksPerB) * (NN_T * NN_Q);

    __shared__ float4 skA[NN_CH / 2];   // (x0,x1,y0,y1)
    __shared__ float4 skB[NN_CH / 2];   // (z0,z1,k2_0,k2_1)

    const int tid = threadIdx.x;
    const int ja = j0 + tid;
    const int jb = j0 + tid + NN_T;

    const float* ua = unknown + ((size_t)b * N_ + ja) * 3;
    const float* ub = unknown + ((size_t)b * N_ + jb) * 3;
    const float ux0 = ua[0], uy0 = ua[1], uz0 = ua[2];
    const float ux1 = ub[0], uy1 = ub[1], uz1 = ub[2];

    const float u20 = __fadd_rn(__fadd_rn(__fmul_rn(ux0, ux0), __fmul_rn(uy0, uy0)),
                                __fmul_rn(uz0, uz0));
    const float u21 = __fadd_rn(__fadd_rn(__fmul_rn(ux1, ux1), __fmul_rn(uy1, uy1)),
                                __fmul_rn(uz1, uz1));

    const u64_t UX0 = pk2(ux0, ux0), UY0 = pk2(uy0, uy0), UZ0 = pk2(uz0, uz0);
    const u64_t UX1 = pk2(ux1, ux1), UY1 = pk2(uy1, uy1), UZ1 = pk2(uz1, uz1);
    const u64_t U20 = pk2(u20, u20), U21 = pk2(u21, u21);
    const u64_t NEG2 = pk2(-2.0f, -2.0f);

    float best0 = INFINITY, best1 = INFINITY;
    int   bi0 = 0, bi1 = 0;

    for (int cb = 0; cb < M_; cb += NN_CH) {
        __syncthreads();
        for (int i = tid; i < NN_CH / 2; i += NN_T) {
            const float* kp = known + ((size_t)b * M_ + cb + 2 * i) * 3;
            const float2 f0 = *(const float2*)(kp + 0);   // x0 y0
            const float2 f1 = *(const float2*)(kp + 2);   // z0 x1
            const float2 f2 = *(const float2*)(kp + 4);   // y1 z1
            const float k20 = __fadd_rn(__fadd_rn(__fmul_rn(f0.x, f0.x), __fmul_rn(f0.y, f0.y)),
                                        __fmul_rn(f1.x, f1.x));
            const float k21 = __fadd_rn(__fadd_rn(__fmul_rn(f1.y, f1.y), __fmul_rn(f2.x, f2.x)),
                                        __fmul_rn(f2.y, f2.y));
            skA[i] = make_float4(f0.x, f1.y, f0.y, f2.x);
            skB[i] = make_float4(f1.x, f2.y, k20, k21);
        }
        __syncthreads();

#pragma unroll 8
        for (int s = 0; s < NN_CH / 2; s++) {
            const ulonglong2 A  = ((const ulonglong2*)skA)[s];  // .x=(x0,x1) .y=(y0,y1)
            const ulonglong2 Bv = ((const ulonglong2*)skB)[s];  // .x=(z0,z1) .y=(k2_0,k2_1)
            u64_t t = mul2(UX0, A.x);
            t = fma2(UY0, A.y, t);
            t = fma2(UZ0, Bv.x, t);
            const u64_t dp0 = add2(fma2(NEG2, t, U20), Bv.y);
            u64_t v = mul2(UX1, A.x);
            v = fma2(UY1, A.y, v);
            v = fma2(UZ1, Bv.x, v);
            const u64_t dp1 = add2(fma2(NEG2, v, U21), Bv.y);
            float dl, dh;
            upk2(dp0, dl, dh);
            if (dl < best0) { best0 = dl; bi0 = cb + 2 * s; }
            if (dh < best0) { best0 = dh; bi0 = cb + 2 * s + 1; }
            upk2(dp1, dl, dh);
            if (dl < best1) { best1 = dl; bi1 = cb + 2 * s; }
            if (dh < best1) { best1 = dh; bi1 = cb + 2 * s + 1; }
        }
    }
    g_idx[(size_t)b * N_ + ja] = bi0;
    g_idx[(size_t)b * N_ + jb] = bi1;
}

// ============================================================================
// Kernel 2: GEMM1 on mma.sync TF32, fused gather+concat + BN1-stat partials.
//   y1t[b][j][c] = sum_k w1[c][k] * X[k][j],  X = concat(gathered kf, uf).
//   CTA: 512 thr (16 warps), tile M(c)=256 x N(j)=128, BK=32 (12 chunks).
//   Warp tile m64 x n32 (wm=wid&3, wn=wid>>2).
// ============================================================================
#define G1_SMEM ((256 * 36 + 128 * 36 + 128) * 4)   // sA + sB + sidx = 55808 B

__global__ __launch_bounds__(512, 1)
void gemm1_mma(const float* __restrict__ kf, const float* __restrict__ uf,
               const float* __restrict__ w1) {
    extern __shared__ float sm[];
    float* sA   = sm;                       // [256][36]
    float* sB   = sm + 256 * 36;            // [128][36]
    int*   sidx = (int*)(sm + 256 * 36 + 128 * 36);

    const int tid = threadIdx.x;
    const int j0  = blockIdx.x * 128;
    const int bb  = blockIdx.y;
    if (tid < 128) sidx[tid] = g_idx[(size_t)bb * N_ + j0 + tid];

    const float* kfb = kf + (size_t)bb * C2_ * M_;
    const float* ufb = uf + (size_t)bb * C1_ * N_;

    const int lane = tid & 31, wid = tid >> 5;
    const int wm = wid & 3, wn = wid >> 2;
    const int g = lane >> 2, t = lane & 3;

    float acc[4][4][4];
#pragma unroll
    for (int i = 0; i < 4; i++)
#pragma unroll
        for (int n = 0; n < 4; n++)
#pragma unroll
            for (int r = 0; r < 4; r++) acc[i][n][r] = 0.f;

    for (int kc = 0; kc < 12; kc++) {
        const int kk = kc * 32;
        __syncthreads();
        // ---- A staging: 256c x 32k, tf32-rounded ----
        {
            const int c = tid >> 1, half = tid & 1;
            const float* src = w1 + (size_t)c * K1_ + kk + half * 16;
            float* dst = sA + c * 36 + half * 16;
#pragma unroll
            for (int i = 0; i < 4; i++) {
                float4 v = *(const float4*)(src + i * 4);
                v.x = tf32r(v.x); v.y = tf32r(v.y); v.z = tf32r(v.z); v.w = tf32r(v.w);
                *(float4*)(dst + i * 4) = v;
            }
        }
        // ---- B staging: 128j x 32k (gather for k<256, stream for k>=256) ----
        {
            const int j = tid & 127, kq = tid >> 7;
            if (kk < C2_) {
                const int col = sidx[j];
#pragma unroll
                for (int i = 0; i < 8; i++)
                    sB[j * 36 + kq * 8 + i] =
                        tf32r(__ldg(kfb + (size_t)(kk + kq * 8 + i) * M_ + col));
            } else {
#pragma unroll
                for (int i = 0; i < 8; i++) {
                    const int kg = kk + kq * 8 + i - C2_;
                    sB[j * 36 + kq * 8 + i] = tf32r(ufb[(size_t)kg * N_ + j0 + j]);
                }
            }
        }
        __syncthreads();
        // ---- 4 k8 MMA steps ----
#pragma unroll
        for (int ks = 0; ks < 4; ks++) {
            const int k = ks * 8;
            uint32_t af[4][4], bf[4][2];
#pragma unroll
            for (int i = 0; i < 4; i++) {
                const float* pa = sA + (wm * 64 + i * 16 + g) * 36 + k + t;
                af[i][0] = __float_as_uint(pa[0]);
                af[i][1] = __float_as_uint(pa[8 * 36]);
                af[i][2] = __float_as_uint(pa[4]);
                af[i][3] = __float_as_uint(pa[8 * 36 + 4]);
            }
#pragma unroll
            for (int nt = 0; nt < 4; nt++) {
                const float* pb = sB + (wn * 32 + nt * 8 + g) * 36 + k + t;
                bf[nt][0] = __float_as_uint(pb[0]);
                bf[nt][1] = __float_as_uint(pb[4]);
            }
#pragma unroll
            for (int i = 0; i < 4; i++)
#pragma unroll
                for (int nt = 0; nt < 4; nt++)
                    mma_tf32(acc[i][nt], af[i], bf[nt]);
        }
    }

    // ---- Epilogue: transpose through smem (reuse sA), coalesced y1t writes ----
    float* E = sA;                      // [32][260]
    const int r  = tid >> 4;            // 0..31
    const int fq = tid & 15;
    for (int p = 0; p < 4; p++) {
        __syncthreads();
        if (wn == p) {
#pragma unroll
            for (int i = 0; i < 4; i++)
#pragma unroll
                for (int nt = 0; nt < 4; nt++) {
                    const int jl = nt * 8 + 2 * t;
                    const int c  = wm * 64 + i * 16 + g;
                    E[jl * 260 + c]           = acc[i][nt][0];
                    E[(jl + 1) * 260 + c]     = acc[i][nt][1];
                    E[jl * 260 + c + 8]       = acc[i][nt][2];
                    E[(jl + 1) * 260 + c + 8] = acc[i][nt][3];
                }
        }
        __syncthreads();
        float* yb = g_y1t + ((size_t)bb * N_ + j0 + p * 32) * H_;
#pragma unroll
        for (int i = 0; i < 4; i++) {
            const int c = (fq + i * 16) * 4;
            *(float4*)(yb + (size_t)r * H_ + c) = *(const float4*)(E + r * 260 + c);
        }
    }

    // ---- Fused BN1-stat partials (deterministic fixed-order reduction) ----
    __syncthreads();                    // done reading E; reuse sm[0..8191]
#pragma unroll
    for (int i = 0; i < 4; i++)
#pragma unroll
        for (int half = 0; half < 2; half++) {
            float s = 0.f, q = 0.f;
#pragma unroll
            for (int nt = 0; nt < 4; nt++)
#pragma unroll
                for (int r2 = 0; r2 < 2; r2++) {
                    const float v = acc[i][nt][half * 2 + r2];
                    s += v; q = fmaf(v, v, q);
                }
            sm[tid * 8 + i * 2 + half]        = s;
            sm[4096 + tid * 8 + i * 2 + half] = q;
        }
    __syncthreads();
    if (tid < 256) {
        const int ch = tid;
        const int cwm = ch >> 6, ci = (ch >> 4) & 3, chalf = (ch >> 3) & 1, cg = ch & 7;
        const int p = ci * 2 + chalf;
        float s = 0.f, q = 0.f;
#pragma unroll
        for (int cwn = 0; cwn < 4; cwn++)
#pragma unroll
            for (int ct = 0; ct < 4; ct++) {
                const int tid2 = (cwn * 4 + cwm) * 32 + cg * 4 + ct;
                s += sm[tid2 * 8 + p];
                q += sm[4096 + tid2 * 8 + p];
            }
        const int blkid = bb * 512 + blockIdx.x;
        g_p1s[ch * 1024 + blkid] = s;
        g_p1q[ch * 1024 + blkid] = q;
    }
}

// ============================================================================
// Kernel 3: finalize BN1 scale/bias from partials. grid=H_, block=256.
// ============================================================================
__global__ __launch_bounds__(256)
void stats1b_kernel(const float* __restrict__ gamma, const float* __restrict__ beta) {
    const int c = blockIdx.x, tid = threadIdx.x;
    float s = 0.f, q = 0.f;
#pragma unroll
    for (int k = 0; k < 4; k++) {
        s += g_p1s[c * 1024 + tid + k * 256];
        q += g_p1q[c * 1024 + tid + k * 256];
    }
    __shared__ float ssum[256], ssq[256];
    ssum[tid] = s; ssq[tid] = q;
    __syncthreads();
    for (int st = 128; st > 0; st >>= 1) {
        if (tid < st) { ssum[tid] += ssum[tid + st]; ssq[tid] += ssq[tid + st]; }
        __syncthreads();
    }
    if (tid == 0) {
        const float inv  = 1.f / (float)(B_ * N_);
        const float mean = ssum[0] * inv;
        const float var  = ssq[0] * inv - mean * mean;
        const float sc   = gamma[c] * rsqrtf(var + EPS_);
        g_s1[c] = sc;
        g_b1[c] = beta[c] - mean * sc;
    }
}

// ============================================================================
// Kernel 4: GEMM2 on mma.sync TF32, BN1+ReLU fused into B staging, BN2-stat
// partials fused into the epilogue. CTA: 512 thr, tile 128c x 128j, K=256.
// Warp tile m64 x n16 (wm=wid&1, wn=wid>>1).
// ============================================================================
__global__ __launch_bounds__(512, 1)
void gemm2_mma(const float* __restrict__ w2, float* __restrict__ out) {
    __shared__ float sA[128 * 36];
    __shared__ float sB[128 * 36];
    __shared__ float ss[H_], sbv[H_];

    const int tid = threadIdx.x;
    const int j0  = blockIdx.x * 128;
    const int bb  = blockIdx.y;
    if (tid < 256) { ss[tid] = g_s1[tid]; sbv[tid] = g_b1[tid]; }

    const float* yb = g_y1t + ((size_t)bb * N_ + j0) * H_;

    const int lane = tid & 31, wid = tid >> 5;
    const int wm = wid & 1, wn = wid >> 1;
    const int g = lane >> 2, t = lane & 3;

    float acc[4][2][4];
#pragma unroll
    for (int i = 0; i < 4; i++)
#pragma unroll
        for (int n = 0; n < 2; n++)
#pragma unroll
            for (int r = 0; r < 4; r++) acc[i][n][r] = 0.f;

    for (int kc = 0; kc < 8; kc++) {
        const int kk = kc * 32;
        __syncthreads();
        // ---- A staging: 128c x 32k ----
        {
            const int c = tid >> 2, part = tid & 3;
            const float* src = w2 + (size_t)c * H_ + kk + part * 8;
            float* dst = sA + c * 36 + part * 8;
#pragma unroll
            for (int i = 0; i < 2; i++) {
                float4 v = *(const float4*)(src + i * 4);
                v.x = tf32r(v.x); v.y = tf32r(v.y); v.z = tf32r(v.z); v.w = tf32r(v.w);
                *(float4*)(dst + i * 4) = v;
            }
        }
        // ---- B staging: 128j x 32k, bn1+relu fused (coalesced float4) ----
        {
            const int j = tid >> 2, part = tid & 3;
            const float* src = yb + (size_t)j * H_ + kk + part * 8;
            float* dst = sB + j * 36 + part * 8;
#pragma unroll
            for (int i = 0; i < 2; i++) {
                const int k = kk + part * 8 + i * 4;
                float4 v = *(const float4*)(src + i * 4);
                v.x = tf32r(fmaxf(fmaf(ss[k],     v.x, sbv[k]),     0.f));
                v.y = tf32r(fmaxf(fmaf(ss[k + 1], v.y, sbv[k + 1]), 0.f));
                v.z = tf32r(fmaxf(fmaf(ss[k + 2], v.z, sbv[k + 2]), 0.f));
                v.w = tf32r(fmaxf(fmaf(ss[k + 3], v.w, sbv[k + 3]), 0.f));
                *(float4*)(dst + i * 4) = v;
            }
        }
        __syncthreads();
#pragma unroll
        for (int ks = 0; ks < 4; ks++) {
            const int k = ks * 8;
            uint32_t af[4][4], bf[2][2];
#pragma unroll
            for (int i = 0; i < 4; i++) {
                const float* pa = sA + (wm * 64 + i * 16 + g) * 36 + k + t;
                af[i][0] = __float_as_uint(pa[0]);
                af[i][1] = __float_as_uint(pa[8 * 36]);
                af[i][2] = __float_as_uint(pa[4]);
                af[i][3] = __float_as_uint(pa[8 * 36 + 4]);
            }
#pragma unroll
            for (int nt = 0; nt < 2; nt++) {
                const float* pb = sB + (wn * 16 + nt * 8 + g) * 36 + k + t;
                bf[nt][0] = __float_as_uint(pb[0]);
                bf[nt][1] = __float_as_uint(pb[4]);
            }
#pragma unroll
            for (int i = 0; i < 4; i++)
#pragma unroll
                for (int nt = 0; nt < 2; nt++)
                    mma_tf32(acc[i][nt], af[i], bf[nt]);
        }
    }

    // ---- Epilogue: direct stores (c-major out rows, j-pairs contiguous) ----
    float* ob = out + (size_t)bb * O_ * N_ + j0;
#pragma unroll
    for (int i = 0; i < 4; i++)
#pragma unroll
        for (int nt = 0; nt < 2; nt++) {
            const int c = wm * 64 + i * 16 + g;
            const int j = wn * 16 + nt * 8 + 2 * t;
            *(float2*)(ob + (size_t)c * N_ + j)       = make_float2(acc[i][nt][0], acc[i][nt][1]);
            *(float2*)(ob + (size_t)(c + 8) * N_ + j) = make_float2(acc[i][nt][2], acc[i][nt][3]);
        }

    // ---- Fused BN2-stat partials (deterministic fixed-order reduction) ----
    __syncthreads();                    // MMA loop done with sA/sB; reuse
#pragma unroll
    for (int i = 0; i < 4; i++)
#pragma unroll
        for (int half = 0; half < 2; half++) {
            float s = 0.f, q = 0.f;
#pragma unroll
            for (int nt = 0; nt < 2; nt++)
#pragma unroll
                for (int r2 = 0; r2 < 2; r2++) {
                    const float v = acc[i][nt][half * 2 + r2];
                    s += v; q = fmaf(v, v, q);
                }
            sA[tid * 8 + i * 2 + half] = s;
            sB[tid * 8 + i * 2 + half] = q;
        }
    __syncthreads();
    if (tid < 128) {
        const int ch = tid;
        const int cwm = ch >> 6, ci = (ch >> 4) & 3, chalf = (ch >> 3) & 1, cg = ch & 7;
        const int p = ci * 2 + chalf;
        float s = 0.f, q = 0.f;
#pragma unroll
        for (int cwn = 0; cwn < 8; cwn++)
#pragma unroll
            for (int ct = 0; ct < 4; ct++) {
                const int tid2 = (cwn * 2 + cwm) * 32 + cg * 4 + ct;
                s += sA[tid2 * 8 + p];
                q += sB[tid2 * 8 + p];
            }
        const int blkid = bb * 512 + blockIdx.x;
        g_p2s[ch * 1024 + blkid] = s;
        g_p2q[ch * 1024 + blkid] = q;
    }
}

// ============================================================================
// Kernel 5: finalize BN2 scale/bias from partials. grid=O_, block=256.
// ============================================================================
__global__ __launch_bounds__(256)
void stats2b_kernel(const float* __restrict__ gamma, const float* __restrict__ beta) {
    const int c = blockIdx.x, tid = threadIdx.x;
    float s = 0.f, q = 0.f;
#pragma unroll
    for (int k = 0; k < 4; k++) {
        s += g_p2s[c * 1024 + tid + k * 256];
        q += g_p2q[c * 1024 + tid + k * 256];
    }
    __shared__ float ssum[256], ssq[256];
    ssum[tid] = s; ssq[tid] = q;
    __syncthreads();
    for (int st = 128; st > 0; st >>= 1) {
        if (tid < st) { ssum[tid] += ssum[tid + st]; ssq[tid] += ssq[tid + st]; }
        __syncthreads();
    }
    if (tid == 0) {
        const float inv  = 1.f / (float)(B_ * N_);
        const float mean = ssum[0] * inv;
        const float var  = ssq[0] * inv - mean * mean;
        const float sc   = gamma[c] * rsqrtf(var + EPS_);
        g_s2[c] = sc;
        g_b2[c] = beta[c] - mean * sc;
    }
}

// ============================================================================
// Kernel 6: in-place BN2 + ReLU on d_out.
// ============================================================================
__global__ __launch_bounds__(256)
void apply2_kernel(float* __restrict__ dout) {
    const size_t total4 = (size_t)B_ * O_ * N_ / 4;
    for (size_t i = (size_t)blockIdx.x * blockDim.x + threadIdx.x; i < total4;
         i += (size_t)gridDim.x * blockDim.x) {
        float4 v = ((float4*)dout)[i];
        const int c = (int)((i * 4) >> 16) & (O_ - 1);   // N_ = 2^16
        const float s = g_s2[c], bb = g_b2[c];
        v.x = fmaxf(fmaf(s, v.x, bb), 0.f);
        v.y = fmaxf(fmaf(s, v.y, bb), 0.f);
        v.z = fmaxf(fmaf(s, v.z, bb), 0.f);
        v.w = fmaxf(fmaf(s, v.w, bb), 0.f);
        ((float4*)dout)[i] = v;
    }
}

// ============================================================================
extern "C" void kernel_launch(void* const* d_in, const int* in_sizes, int n_in,
                              void* d_out, int out_size) {
    (void)in_sizes; (void)n_in; (void)out_size;
    const float* unknown = (const float*)d_in[0];
    const float* known   = (const float*)d_in[1];
    const float* uf      = (const float*)d_in[2];
    const float* kf      = (const float*)d_in[3];
    const float* w1      = (const float*)d_in[4];
    const float* gamma1  = (const float*)d_in[5];
    const float* beta1   = (const float*)d_in[6];
    const float* w2      = (const float*)d_in[7];
    const float* gamma2  = (const float*)d_in[8];
    const float* beta2   = (const float*)d_in[9];
    float* out = (float*)d_out;

    static int s_init = 0;
    if (!s_init) {
        cudaFuncSetAttribute(gemm1_mma, cudaFuncAttributeMaxDynamicSharedMemorySize, G1_SMEM);
        s_init = 1;
    }

    nn_kernel<<<(B_ * N_) / (NN_T * NN_Q), NN_T>>>(unknown, known);
    gemm1_mma<<<dim3(N_ / 128, B_), 512, G1_SMEM>>>(kf, uf, w1);
    stats1b_kernel<<<H_, 256>>>(gamma1, beta1);
    gemm2_mma<<<dim3(N_ / 128, B_), 512>>>(w2, out);
    stats2b_kernel<<<O_, 256>>>(gamma2, beta2);
    apply2_kernel<<<2048, 256>>>(out);
}